// round 2
// baseline (speedup 1.0000x reference)
#include <cuda_runtime.h>

// Problem constants
#define NH     16       // heads
#define DK     64
#define DV     64
#define NSAMP  16384    // B*S = 4*4096
#define NSPLIT 32       // split-K factor per head
#define CHUNK  (NSAMP / NSPLIT)   // 512 samples per CTA
#define KS     32       // panel size (samples staged in smem per iteration)
#define NPANEL (CHUNK / KS)       // 16
#define DECAYF 0.95f

// Deterministic split-K partials: [NSPLIT][NH][DK][DV] = 8 MB static scratch
__device__ float g_partial[NSPLIT * NH * DK * DV];

__global__ __launch_bounds__(256, 2)
void l1writer_gemm_kernel(const float* __restrict__ keys,
                          const float* __restrict__ values,
                          const float* __restrict__ rho)
{
    __shared__ float ks[KS][DK];
    __shared__ float vs[KS][DV];

    const int split = blockIdx.x;   // 0..NSPLIT-1
    const int h     = blockIdx.y;   // 0..NH-1
    const int tid   = threadIdx.x;  // 0..255
    const int n0    = split * CHUNK;

    // Compute-phase mapping: 16x16 thread grid, 4x4 regs each -> 64x64 tile
    const int ty = tid >> 4;   // k-row group
    const int tx = tid & 15;   // v-col group

    float acc[4][4];
#pragma unroll
    for (int i = 0; i < 4; i++)
#pragma unroll
        for (int j = 0; j < 4; j++) acc[i][j] = 0.f;

    // Loader mapping: 512 float4s per array per panel; each thread carries 2.
    float4 kreg[2], vreg[2];
    float  rreg[2];

    // Prefetch panel 0
#pragma unroll
    for (int j = 0; j < 2; j++) {
        int idx  = tid + j * 256;
        int smp  = idx >> 4;           // 0..31
        int lane = idx & 15;           // float4 lane in row
        int n    = n0 + smp;
        long off = ((long)n * NH + h) * 64 + lane * 4;
        kreg[j] = *(const float4*)(keys   + off);
        vreg[j] = *(const float4*)(values + off);
        rreg[j] = __ldg(rho + n);
    }

    for (int p = 0; p < NPANEL; ++p) {
        // Commit prefetched panel to smem (scale k by rho here)
#pragma unroll
        for (int j = 0; j < 2; j++) {
            int idx  = tid + j * 256;
            int smp  = idx >> 4;
            int lane = idx & 15;
            float  r  = rreg[j];
            float4 k4 = kreg[j];
            k4.x *= r; k4.y *= r; k4.z *= r; k4.w *= r;
            *(float4*)&ks[smp][lane * 4] = k4;
            *(float4*)&vs[smp][lane * 4] = vreg[j];
        }
        __syncthreads();

        // Prefetch next panel (LDG latency hides under the 512-FFMA block below)
        if (p + 1 < NPANEL) {
#pragma unroll
            for (int j = 0; j < 2; j++) {
                int idx  = tid + j * 256;
                int smp  = idx >> 4;
                int lane = idx & 15;
                int n    = n0 + (p + 1) * KS + smp;
                long off = ((long)n * NH + h) * 64 + lane * 4;
                kreg[j] = *(const float4*)(keys   + off);
                vreg[j] = *(const float4*)(values + off);
                rreg[j] = __ldg(rho + n);
            }
        }

        // Rank-KS update of the 4x4 register tile
#pragma unroll
        for (int kk = 0; kk < KS; ++kk) {
            float4 a = *(const float4*)&ks[kk][ty * 4];
            float4 b = *(const float4*)&vs[kk][tx * 4];
            acc[0][0] += a.x * b.x; acc[0][1] += a.x * b.y;
            acc[0][2] += a.x * b.z; acc[0][3] += a.x * b.w;
            acc[1][0] += a.y * b.x; acc[1][1] += a.y * b.y;
            acc[1][2] += a.y * b.z; acc[1][3] += a.y * b.w;
            acc[2][0] += a.z * b.x; acc[2][1] += a.z * b.y;
            acc[2][2] += a.z * b.z; acc[2][3] += a.z * b.w;
            acc[3][0] += a.w * b.x; acc[3][1] += a.w * b.y;
            acc[3][2] += a.w * b.z; acc[3][3] += a.w * b.w;
        }
        __syncthreads();
    }

    // Write deterministic partial tile
    float* outp = g_partial + ((size_t)(split * NH + h)) * (DK * DV);
#pragma unroll
    for (int i = 0; i < 4; i++) {
        float4 r = make_float4(acc[i][0], acc[i][1], acc[i][2], acc[i][3]);
        *(float4*)&outp[(ty * 4 + i) * DV + tx * 4] = r;
    }
}

// out = 0.95*memory + sum_p partial[p]   (65536 floats = 16384 float4)
__global__ __launch_bounds__(256)
void l1writer_reduce_kernel(const float* __restrict__ memory,
                            float* __restrict__ out)
{
    int i = blockIdx.x * blockDim.x + threadIdx.x;  // float4 index, 0..16383
    const float4* m4 = (const float4*)memory;
    float4 m = m4[i];
    float4 acc;
    acc.x = DECAYF * m.x; acc.y = DECAYF * m.y;
    acc.z = DECAYF * m.z; acc.w = DECAYF * m.w;
    const float4* p4 = (const float4*)g_partial;
#pragma unroll
    for (int p = 0; p < NSPLIT; ++p) {
        float4 v = p4[(size_t)p * (NH * DK * DV / 4) + i];
        acc.x += v.x; acc.y += v.y; acc.z += v.z; acc.w += v.w;
    }
    ((float4*)out)[i] = acc;
}

extern "C" void kernel_launch(void* const* d_in, const int* in_sizes, int n_in,
                              void* d_out, int out_size)
{
    const float* memory = (const float*)d_in[0];  // (16,64,64)
    const float* keys   = (const float*)d_in[1];  // (4,4096,16,64)
    const float* values = (const float*)d_in[2];  // (4,4096,16,64)
    const float* rho    = (const float*)d_in[3];  // (4,4096)
    float* out = (float*)d_out;                   // (16,64,64)

    dim3 grid(NSPLIT, NH);
    l1writer_gemm_kernel<<<grid, 256>>>(keys, values, rho);
    l1writer_reduce_kernel<<<(NH * DK * DV / 4 + 255) / 256, 256>>>(memory, out);
}